// round 13
// baseline (speedup 1.0000x reference)
#include <cuda_runtime.h>
#include <cuda_bf16.h>
#include <cstdint>

#define B_ROWS 4096
#define D_DIM  768
#define F_DIM  24576
#define TOPK   32
#define NCAND  40
#define NTILE  192          // F_DIM / 128

// dynamic smem layout for enc_gemm: 3xA (30720) + 3xB (30720) + tmax (4352)
#define SM_A_OFF   0
#define SM_B_OFF   30720
#define SM_T_OFF   61440
#define SM_TOTAL   65792

// ---------------- scratch (device globals; no runtime allocation) ----------
__device__ __nv_bfloat16 g_Hb[(size_t)B_ROWS * F_DIM];   // approx pre-acts (bf16)
__device__ float         g_WT[(size_t)F_DIM * D_DIM];    // W_enc^T fp32 (exact path)
__device__ __nv_bfloat16 g_Wb[(size_t)F_DIM * D_DIM];    // W_enc^T bf16 (mma B operand)
__device__ __nv_bfloat16 g_Xb[(size_t)B_ROWS * D_DIM];   // bf16(x - b_pre)
__device__ unsigned short g_tmax[(size_t)B_ROWS * NTILE]; // per-row per-tile max (bf16 bits)
__device__ unsigned short g_tlist[(size_t)B_ROWS * NTILE];// qualifying tile list
__device__ int   g_tcnt[B_ROWS];
__device__ int   g_ci[B_ROWS * NCAND];
__device__ float g_tv[B_ROWS * TOPK];
__device__ int   g_ti[B_ROWS * TOPK];

// ---------------- helpers ---------------------------------------------------
__device__ __forceinline__ uint32_t smem_u32(const void* p) {
    uint32_t a;
    asm("{ .reg .u64 t; cvta.to.shared.u64 t, %1; cvt.u32.u64 %0, t; }" : "=r"(a) : "l"(p));
    return a;
}
__device__ __forceinline__ uint32_t pack_bf2(float lo, float hi) {
    __nv_bfloat162 h2 = __floats2bfloat162_rn(lo, hi);
    return *reinterpret_cast<uint32_t*>(&h2);
}

#define LDSM_X4(r, addr)                                                       \
    asm volatile("ldmatrix.sync.aligned.m8n8.x4.shared.b16 {%0,%1,%2,%3}, [%4];" \
        : "=r"((r)[0]), "=r"((r)[1]), "=r"((r)[2]), "=r"((r)[3]) : "r"(addr))

#define MMA16816(d, a, b0, b1)                                                 \
    asm volatile("mma.sync.aligned.m16n8k16.row.col.f32.bf16.bf16.f32 "        \
        "{%0,%1,%2,%3}, {%4,%5,%6,%7}, {%8,%9}, {%0,%1,%2,%3};"                \
        : "+f"((d)[0]), "+f"((d)[1]), "+f"((d)[2]), "+f"((d)[3])               \
        : "r"((a)[0]), "r"((a)[1]), "r"((a)[2]), "r"((a)[3]),                  \
          "r"(b0), "r"(b1))

#define CP_ASYNC16(dst, src)                                                   \
    asm volatile("cp.async.ca.shared.global [%0], [%1], 16;"                   \
                 :: "r"(dst), "l"(src) : "memory")
#define CP_COMMIT()  asm volatile("cp.async.commit_group;" ::: "memory")
#define CP_WAIT1()   asm volatile("cp.async.wait_group 1;" ::: "memory")
#define CP_WAIT0()   asm volatile("cp.async.wait_group 0;" ::: "memory")

// top-3 key-cache insert
#define K3_INSERT(key)                                                         \
    do { if ((key) > k3) {                                                     \
            if ((key) > k1)      { k3 = k2; k2 = k1; k1 = (key); }             \
            else if ((key) > k2) { k3 = k2; k2 = (key); }                      \
            else                 { k3 = (key); }                               \
    } } while (0)

// ---------------------------------------------------------------------------
// prep_x: Xb = bf16(x - b_pre)
// ---------------------------------------------------------------------------
__global__ void prep_x(const float* __restrict__ X, const float* __restrict__ b_pre,
                       __nv_bfloat16* __restrict__ Xb)
{
    const int idx = blockIdx.x * blockDim.x + threadIdx.x;   // B*D/4 total
    const int d4  = idx % (D_DIM / 4);
    float4 x4 = reinterpret_cast<const float4*>(X)[idx];
    float4 bp = reinterpret_cast<const float4*>(b_pre)[d4];
    uint32_t lo = pack_bf2(x4.x - bp.x, x4.y - bp.y);
    uint32_t hi = pack_bf2(x4.z - bp.z, x4.w - bp.w);
    reinterpret_cast<uint2*>(Xb)[idx] = make_uint2(lo, hi);
}

// ---------------------------------------------------------------------------
// Transpose W_enc [D, F] -> WT fp32 [F, D] and Wb bf16 [F, D]
// ---------------------------------------------------------------------------
__global__ void transpose_kernel(const float* __restrict__ W, float* __restrict__ WT,
                                 __nv_bfloat16* __restrict__ Wb)
{
    __shared__ float tile[32][33];
    const int f0 = blockIdx.x * 32, d0 = blockIdx.y * 32;
    const int tx = threadIdx.x, ty = threadIdx.y;   // 32 x 8
    #pragma unroll
    for (int i = 0; i < 4; i++)
        tile[ty + 8 * i][tx] = W[(size_t)(d0 + ty + 8 * i) * F_DIM + f0 + tx];
    __syncthreads();
    #pragma unroll
    for (int i = 0; i < 4; i++) {
        float v = tile[tx][ty + 8 * i];
        size_t o = (size_t)(f0 + ty + 8 * i) * D_DIM + d0 + tx;
        WT[o] = v;
        Wb[o] = __float2bfloat16(v);
    }
}

// ---------------------------------------------------------------------------
// Encoder GEMM via mma.sync bf16: Hb = bf16(relu(Xb @ Wb^T + b_enc)),
// plus per-row tile maxima into g_tmax.
// 3-stage cp.async pipeline, ONE __syncthreads per K-iter, dynamic smem.
// ---------------------------------------------------------------------------
__global__ __launch_bounds__(256, 2)
void enc_gemm_mma(const __nv_bfloat16* __restrict__ Xb,
                  const __nv_bfloat16* __restrict__ Wb,
                  const float* __restrict__ b_enc,
                  __nv_bfloat16* __restrict__ Hb)
{
    extern __shared__ __align__(16) char smem_raw[];
    unsigned short* tmaxs = reinterpret_cast<unsigned short*>(smem_raw + SM_T_OFF);

    const int tid = threadIdx.x, wid = tid >> 5, lane = tid & 31;
    const int row0 = blockIdx.x * 128, col0 = blockIdx.y * 128;
    const int warp_m = wid >> 2, warp_n = wid & 3;

    float acc[4][4][4];
    #pragma unroll
    for (int i = 0; i < 4; i++)
        #pragma unroll
        for (int j = 0; j < 4; j++)
            #pragma unroll
            for (int q = 0; q < 4; q++) acc[i][j][q] = 0.0f;

    const uint32_t sbase = smem_u32(smem_raw);
    uint32_t sA3[3], sB3[3];
    #pragma unroll
    for (int s = 0; s < 3; s++) {
        sA3[s] = sbase + SM_A_OFF + s * 10240;
        sB3[s] = sbase + SM_B_OFF + s * 10240;
    }

    const int lr0 = tid >> 2, lc0 = tid & 3;
    const int lr1 = (tid + 256) >> 2, lc1 = lc0;

    #define ISSUE(c, buf) do {                                                 \
        const int _k0 = (c) * 32;                                              \
        const __nv_bfloat16* aA0 = Xb + (size_t)(row0 + lr0) * D_DIM + _k0 + lc0 * 8; \
        const __nv_bfloat16* aA1 = Xb + (size_t)(row0 + lr1) * D_DIM + _k0 + lc1 * 8; \
        const __nv_bfloat16* aB0 = Wb + (size_t)(col0 + lr0) * D_DIM + _k0 + lc0 * 8; \
        const __nv_bfloat16* aB1 = Wb + (size_t)(col0 + lr1) * D_DIM + _k0 + lc1 * 8; \
        CP_ASYNC16(sA3[buf] + lr0 * 80 + lc0 * 16, aA0);                       \
        CP_ASYNC16(sA3[buf] + lr1 * 80 + lc1 * 16, aA1);                       \
        CP_ASYNC16(sB3[buf] + lr0 * 80 + lc0 * 16, aB0);                       \
        CP_ASYNC16(sB3[buf] + lr1 * 80 + lc1 * 16, aB1);                       \
        CP_COMMIT();                                                           \
    } while (0)

    ISSUE(0, 0);
    ISSUE(1, 1);

    for (int c = 0; c < 24; c++) {
        // chunk c resident after this (groups complete in order; <=1 pending)
        if (c < 23) CP_WAIT1(); else CP_WAIT0();
        __syncthreads();           // (a) chunk-c data visible to all threads
                                   // (b) all readers of buf (c-1)%3 are done
        if (c + 2 < 24) ISSUE(c + 2, (c + 2) % 3);   // writes buf (c-1)%3

        const uint32_t sa = sA3[c % 3], sb = sB3[c % 3];
        #pragma unroll
        for (int ks = 0; ks < 2; ks++) {
            uint32_t a[4][4], b[2][4];
            const uint32_t koff = (uint32_t)((ks * 16 + (lane >> 4) * 8) * 2);
            #pragma unroll
            for (int mf = 0; mf < 4; mf++) {
                const uint32_t r = (uint32_t)(warp_m * 64 + mf * 16 + (lane & 15));
                LDSM_X4(a[mf], sa + r * 80 + koff);
            }
            #pragma unroll
            for (int np = 0; np < 2; np++) {
                const uint32_t r = (uint32_t)(warp_n * 32 + np * 16 + (lane & 15));
                LDSM_X4(b[np], sb + r * 80 + koff);
            }
            #pragma unroll
            for (int mf = 0; mf < 4; mf++) {
                #pragma unroll
                for (int np = 0; np < 2; np++) {
                    MMA16816(acc[mf][np * 2 + 0], a[mf], b[np][0], b[np][2]);
                    MMA16816(acc[mf][np * 2 + 1], a[mf], b[np][1], b[np][3]);
                }
            }
        }
    }
    #undef ISSUE
    __syncthreads();   // all compute done before tmaxs reuse of smem region

    // epilogue: + b_enc, relu, bf16 store; accumulate per-thread row maxima
    const int lr = lane >> 2, lc = (lane & 3) * 2;
    float rmax[8];
    #pragma unroll
    for (int i = 0; i < 8; i++) rmax[i] = 0.0f;   // relu => values >= 0

    #pragma unroll
    for (int nf = 0; nf < 4; nf++) {
        const int col = col0 + warp_n * 32 + nf * 8 + lc;
        const float e0 = b_enc[col], e1 = b_enc[col + 1];
        #pragma unroll
        for (int mf = 0; mf < 4; mf++) {
            const int row = row0 + warp_m * 64 + mf * 16 + lr;
            float v0 = fmaxf(acc[mf][nf][0] + e0, 0.0f);
            float v1 = fmaxf(acc[mf][nf][1] + e1, 0.0f);
            float v2 = fmaxf(acc[mf][nf][2] + e0, 0.0f);
            float v3 = fmaxf(acc[mf][nf][3] + e1, 0.0f);
            rmax[2 * mf]     = fmaxf(rmax[2 * mf],     fmaxf(v0, v1));
            rmax[2 * mf + 1] = fmaxf(rmax[2 * mf + 1], fmaxf(v2, v3));
            *reinterpret_cast<uint32_t*>(Hb + (size_t)row * F_DIM + col)       = pack_bf2(v0, v1);
            *reinterpret_cast<uint32_t*>(Hb + (size_t)(row + 8) * F_DIM + col) = pack_bf2(v2, v3);
        }
    }

    // per-row tile max: 16 slots per row (4 warp_n x 4 lane-groups)
    const int slot = warp_n * 4 + (lane & 3);
    #pragma unroll
    for (int i = 0; i < 8; i++) {
        const int r = warp_m * 64 + (i >> 1) * 16 + lr + (i & 1) * 8;
        tmaxs[r * 17 + slot] = __bfloat16_as_ushort(__float2bfloat16(rmax[i]));
    }
    __syncthreads();
    if (tid < 128) {
        unsigned short m = 0;
        #pragma unroll
        for (int s = 0; s < 16; s++) m = max(m, tmaxs[tid * 17 + s]);
        g_tmax[(size_t)(row0 + tid) * NTILE + blockIdx.y] = m;
    }
}

// ---------------------------------------------------------------------------
// sel_a: per row, tau = 40th-largest tile max; emit qualifying tile list.
// ---------------------------------------------------------------------------
__global__ __launch_bounds__(256)
void sel_a()
{
    const int warp = threadIdx.x >> 5, lane = threadIdx.x & 31;
    const int row = blockIdx.x * 8 + warp;
    __shared__ int cnt[8];
    if (lane == 0) cnt[warp] = 0;
    __syncwarp();

    uint32_t tmv[6];
    uint32_t k1 = 0u, k2 = 0u, k3 = 0u;
    #pragma unroll
    for (int i = 0; i < 6; i++) {
        tmv[i] = (uint32_t)g_tmax[(size_t)row * NTILE + i * 32 + lane];
        const uint32_t key = (tmv[i] << 8) | (uint32_t)(255 - (i * 32 + lane));
        K3_INSERT(key);
    }

    uint32_t tau = 0u;
    uint32_t lastpop = 0xffffffffu;
    for (int r = 0; r < NCAND; r++) {
        const uint32_t wk = __reduce_max_sync(0xffffffffu, k1);
        if (r == NCAND - 1) tau = wk >> 8;
        if (k1 == wk && wk != 0u) {
            lastpop = wk;
            if (k2 != 0u) { k1 = k2; k2 = k3; k3 = 0u; }
            else {
                k1 = k2 = k3 = 0u;
                #pragma unroll
                for (int i = 0; i < 6; i++) {
                    const uint32_t key = (tmv[i] << 8) | (uint32_t)(255 - (i * 32 + lane));
                    if (key < lastpop) K3_INSERT(key);
                }
            }
        }
    }

    #pragma unroll
    for (int i = 0; i < 6; i++)
        if (tmv[i] >= tau) {
            const int p = atomicAdd(&cnt[warp], 1);
            g_tlist[(size_t)row * NTILE + p] = (unsigned short)(i * 32 + lane);
        }
    __syncwarp();
    if (lane == 0) g_tcnt[row] = cnt[warp];
}

// ---------------------------------------------------------------------------
// sel_b: exact top-NCAND (value desc, index asc) over the qualifying tiles.
// ---------------------------------------------------------------------------
__global__ __launch_bounds__(256)
void sel_b(const __nv_bfloat16* __restrict__ Hb)
{
    const int row = blockIdx.x;
    const int t = threadIdx.x, lane = t & 31, warp = t >> 5;

    __shared__ unsigned short tl[NTILE];
    __shared__ int s_nt;
    __shared__ uint32_t cand[8 * NCAND];

    if (t == 0) s_nt = g_tcnt[row];
    __syncthreads();
    const int nt = s_nt;
    if (t < nt) tl[t] = g_tlist[(size_t)row * NTILE + t];
    __syncthreads();

    const uint4* __restrict__ hrow =
        reinterpret_cast<const uint4*>(Hb + (size_t)row * F_DIM);
    const int nq = nt * 16;           // uint4 chunks over listed tiles

    uint32_t k1 = 0u, k2 = 0u, k3 = 0u;
    for (int q = t; q < nq; q += 256) {
        const uint32_t u = (uint32_t)tl[q >> 4] * 16u + (uint32_t)(q & 15);
        uint4 d = hrow[u];
        uint32_t ws[4] = { d.x, d.y, d.z, d.w };
        #pragma unroll
        for (int w = 0; w < 4; w++) {
            #pragma unroll
            for (int e = 0; e < 2; e++) {
                const uint32_t vb  = e ? (ws[w] >> 16) : (ws[w] & 0xffffu);
                const uint32_t key = (vb << 15) | (uint32_t)(24575u - (u * 8u + (uint32_t)(w * 2 + e)));
                K3_INSERT(key);
            }
        }
    }

    uint32_t lastpop = 0xffffffffu;
    for (int r = 0; r < NCAND; r++) {
        const uint32_t wk = __reduce_max_sync(0xffffffffu, k1);
        if (lane == 0) cand[warp * NCAND + r] = wk;
        if (k1 == wk && wk != 0u) {
            lastpop = wk;
            if (k2 != 0u) { k1 = k2; k2 = k3; k3 = 0u; }
            else {
                k1 = k2 = k3 = 0u;
                for (int q = t; q < nq; q += 256) {
                    const uint32_t u = (uint32_t)tl[q >> 4] * 16u + (uint32_t)(q & 15);
                    uint4 d = hrow[u];
                    uint32_t ws[4] = { d.x, d.y, d.z, d.w };
                    #pragma unroll
                    for (int w = 0; w < 4; w++) {
                        #pragma unroll
                        for (int e = 0; e < 2; e++) {
                            const uint32_t vb  = e ? (ws[w] >> 16) : (ws[w] & 0xffffu);
                            const uint32_t key = (vb << 15) | (uint32_t)(24575u - (u * 8u + (uint32_t)(w * 2 + e)));
                            if (key < lastpop) K3_INSERT(key);
                        }
                    }
                }
            }
        }
    }
    __syncthreads();

    // warp 0 merges 8x40 -> block top-40 (keys globally unique)
    if (warp == 0) {
        uint32_t c[10];
        #pragma unroll
        for (int i = 0; i < 10; i++) c[i] = cand[i * 32 + lane];
        for (int r = 0; r < NCAND; r++) {
            uint32_t loc = 0u;
            #pragma unroll
            for (int i = 0; i < 10; i++) loc = max(loc, c[i]);
            const uint32_t best = __reduce_max_sync(0xffffffffu, loc);
            #pragma unroll
            for (int i = 0; i < 10; i++) if (c[i] == best) c[i] = 0u;
            if (lane == 0)
                g_ci[row * NCAND + r] = (int)(24575u - (best & 0x7fffu));
        }
    }
}

// ---------------------------------------------------------------------------
__global__ void zero_kernel(float4* __restrict__ p, size_t n4)
{
    size_t i = (size_t)blockIdx.x * blockDim.x + threadIdx.x;
    const size_t stride = (size_t)gridDim.x * blockDim.x;
    for (; i < n4; i += stride) p[i] = make_float4(0.f, 0.f, 0.f, 0.f);
}

// ---------------------------------------------------------------------------
// Exact recompute, BIT-IDENTICAL to the round-1 fp32 path.
// ---------------------------------------------------------------------------
__global__ __launch_bounds__(320)
void exact_seq(const float* __restrict__ X, const float* __restrict__ b_pre,
               const float* __restrict__ WT, const float* __restrict__ b_enc,
               float* __restrict__ Hout)
{
    const int r0 = blockIdx.x * 8;
    const int t = threadIdx.x;
    const int lane = t & 31, w = t >> 5;

    __shared__ float xs[8][D_DIM];
    __shared__ float cv[8][NCAND];
    __shared__ int   ci[8][NCAND];

    for (int i = t; i < 8 * D_DIM; i += 320) {
        const int rr = i / D_DIM, k = i % D_DIM;
        xs[rr][k] = X[(size_t)(r0 + rr) * D_DIM + k] - b_pre[k];
    }
    if (t < 8 * NCAND) ci[t / NCAND][t % NCAND] = g_ci[(size_t)(r0 + t / NCAND) * NCAND + t % NCAND];
    __syncthreads();

    {   // all 320 threads: one candidate each, strict sequential fp32 chain
        const int rr = t / NCAND, c = t % NCAND;
        const int f = ci[rr][c];
        const float* __restrict__ wt = WT + (size_t)f * D_DIM;
        const float* __restrict__ xr = xs[rr];
        float s = 0.0f;
        #pragma unroll 4
        for (int k4 = 0; k4 < D_DIM / 4; k4++) {
            float4 w4 = reinterpret_cast<const float4*>(wt)[k4];
            float4 x4 = reinterpret_cast<const float4*>(xr)[k4];
            s = fmaf(w4.x, x4.x, s);
            s = fmaf(w4.y, x4.y, s);
            s = fmaf(w4.z, x4.z, s);
            s = fmaf(w4.w, x4.w, s);
        }
        cv[rr][c] = fmaxf(s + b_enc[f], 0.0f);
    }
    __syncthreads();

    // warps 0..7: exact top-32 of this row's 40 candidates (ties -> lower idx)
    if (w < 8) {
        const int row = r0 + w;
        uint64_t used = 0ull;
        for (int r2 = 0; r2 < TOPK; r2++) {
            float v = -1.0f; int idx = 0x7fffffff; int jslot = 63;
            {
                int j0 = lane;
                if (!((used >> j0) & 1ull)) { v = cv[w][j0]; idx = ci[w][j0]; jslot = j0; }
                if (lane < NCAND - 32) {
                    int j1 = 32 + lane;
                    if (!((used >> j1) & 1ull)) {
                        float v1 = cv[w][j1]; int k1 = ci[w][j1];
                        if (v1 > v || (v1 == v && k1 < idx)) { v = v1; idx = k1; jslot = j1; }
                    }
                }
            }
            #pragma unroll
            for (int s = 16; s > 0; s >>= 1) {
                float ov = __shfl_down_sync(0xffffffffu, v, s);
                int   oi = __shfl_down_sync(0xffffffffu, idx, s);
                int   oj = __shfl_down_sync(0xffffffffu, jslot, s);
                if (ov > v || (ov == v && oi < idx)) { v = ov; idx = oi; jslot = oj; }
            }
            int winj = __shfl_sync(0xffffffffu, jslot, 0);
            if (lane == 0) {
                g_tv[row * TOPK + r2] = v;
                g_ti[row * TOPK + r2] = idx;
                Hout[(size_t)row * F_DIM + idx] = v;
            }
            used |= (1ull << winj);
        }
    }
}

// ---------------------------------------------------------------------------
__global__ __launch_bounds__(256)
void dec_kernel(const float* __restrict__ Wd, const float* __restrict__ b_dec,
                float* __restrict__ Xhat)
{
    const int row = blockIdx.x;
    const int t = threadIdx.x;
    __shared__ float sv[TOPK];
    __shared__ int   si[TOPK];
    if (t < TOPK) { sv[t] = g_tv[row * TOPK + t]; si[t] = g_ti[row * TOPK + t]; }
    __syncthreads();

    float a0 = b_dec[t], a1 = b_dec[t + 256], a2 = b_dec[t + 512];
    #pragma unroll
    for (int j = 0; j < TOPK; j++) {
        const float* __restrict__ wr = Wd + (size_t)si[j] * D_DIM;
        float v = sv[j];
        a0 += v * wr[t];
        a1 += v * wr[t + 256];
        a2 += v * wr[t + 512];
    }
    float* __restrict__ xr = Xhat + (size_t)row * D_DIM;
    xr[t] = a0; xr[t + 256] = a1; xr[t + 512] = a2;
}

// ---------------------------------------------------------------------------
extern "C" void kernel_launch(void* const* d_in, const int* in_sizes, int n_in,
                              void* d_out, int out_size)
{
    const float* x     = (const float*)d_in[0];
    const float* b_pre = (const float*)d_in[1];
    const float* W_enc = (const float*)d_in[2];
    const float* b_enc = (const float*)d_in[3];
    const float* W_dec = (const float*)d_in[4];
    const float* b_dec = (const float*)d_in[5];
    float* out = (float*)d_out;

    const size_t needH = (size_t)B_ROWS * F_DIM;
    const size_t needX = (size_t)B_ROWS * D_DIM;
    float* H    = out;                            // out holds h (+ x_hat)
    float* Xhat = ((size_t)out_size >= needH + needX) ? out + needH : nullptr;

    float* WT = nullptr;          cudaGetSymbolAddress((void**)&WT, g_WT);
    __nv_bfloat16* Wb = nullptr;  cudaGetSymbolAddress((void**)&Wb, g_Wb);
    __nv_bfloat16* Xb = nullptr;  cudaGetSymbolAddress((void**)&Xb, g_Xb);
    __nv_bfloat16* Hb = nullptr;  cudaGetSymbolAddress((void**)&Hb, g_Hb);

    cudaFuncSetAttribute(enc_gemm_mma,
                         cudaFuncAttributeMaxDynamicSharedMemorySize, SM_TOTAL);

    prep_x<<<(B_ROWS * D_DIM / 4) / 256, 256>>>(x, b_pre, Xb);
    transpose_kernel<<<dim3(F_DIM / 32, D_DIM / 32), dim3(32, 8)>>>(W_enc, WT, Wb);
    enc_gemm_mma<<<dim3(B_ROWS / 128, F_DIM / 128), 256, SM_TOTAL>>>(Xb, Wb, b_enc, Hb);
    sel_a<<<B_ROWS / 8, 256>>>();
    sel_b<<<B_ROWS, 256>>>(Hb);
    zero_kernel<<<12288, 256>>>(reinterpret_cast<float4*>(H), needH / 4);
    exact_seq<<<B_ROWS / 8, 320>>>(x, b_pre, WT, b_enc, H);
    if (Xhat) dec_kernel<<<B_ROWS, 256>>>(W_dec, b_dec, Xhat);
}

// round 14
// speedup vs baseline: 1.0522x; 1.0522x over previous
#include <cuda_runtime.h>
#include <cuda_bf16.h>
#include <cstdint>

#define B_ROWS 4096
#define D_DIM  768
#define F_DIM  24576
#define TOPK   32
#define NCAND  40
#define NTILE  192          // F_DIM / 128

// ---------------- scratch (device globals; no runtime allocation) ----------
__device__ __nv_bfloat16 g_Hb[(size_t)B_ROWS * F_DIM];   // approx pre-acts (bf16)
__device__ float         g_WT[(size_t)F_DIM * D_DIM];    // W_enc^T fp32 (exact path)
__device__ __nv_bfloat16 g_Wb[(size_t)F_DIM * D_DIM];    // W_enc^T bf16 (mma B operand)
__device__ __nv_bfloat16 g_Xb[(size_t)B_ROWS * D_DIM];   // bf16(x - b_pre)
__device__ unsigned short g_tmax[(size_t)B_ROWS * NTILE]; // per-row per-tile max (bf16 bits)
__device__ unsigned short g_tlist[(size_t)B_ROWS * NTILE];// qualifying tile list
__device__ int   g_tcnt[B_ROWS];
__device__ int   g_ci[B_ROWS * NCAND];
__device__ float g_tv[B_ROWS * TOPK];
__device__ int   g_ti[B_ROWS * TOPK];

// ---------------- helpers ---------------------------------------------------
__device__ __forceinline__ uint32_t smem_u32(const void* p) {
    uint32_t a;
    asm("{ .reg .u64 t; cvta.to.shared.u64 t, %1; cvt.u32.u64 %0, t; }" : "=r"(a) : "l"(p));
    return a;
}
__device__ __forceinline__ uint32_t pack_bf2(float lo, float hi) {
    __nv_bfloat162 h2 = __floats2bfloat162_rn(lo, hi);
    return *reinterpret_cast<uint32_t*>(&h2);
}

#define LDSM_X4(r, addr)                                                       \
    asm volatile("ldmatrix.sync.aligned.m8n8.x4.shared.b16 {%0,%1,%2,%3}, [%4];" \
        : "=r"((r)[0]), "=r"((r)[1]), "=r"((r)[2]), "=r"((r)[3]) : "r"(addr))

#define MMA16816(d, a, b0, b1)                                                 \
    asm volatile("mma.sync.aligned.m16n8k16.row.col.f32.bf16.bf16.f32 "        \
        "{%0,%1,%2,%3}, {%4,%5,%6,%7}, {%8,%9}, {%0,%1,%2,%3};"                \
        : "+f"((d)[0]), "+f"((d)[1]), "+f"((d)[2]), "+f"((d)[3])               \
        : "r"((a)[0]), "r"((a)[1]), "r"((a)[2]), "r"((a)[3]),                  \
          "r"(b0), "r"(b1))

#define CP_ASYNC16(dst, src)                                                   \
    asm volatile("cp.async.ca.shared.global [%0], [%1], 16;"                   \
                 :: "r"(dst), "l"(src) : "memory")
#define CP_COMMIT()  asm volatile("cp.async.commit_group;" ::: "memory")
#define CP_WAIT(n)   asm volatile("cp.async.wait_group %0;" :: "n"(n) : "memory")

// top-3 key-cache insert
#define K3_INSERT(key)                                                         \
    do { if ((key) > k3) {                                                     \
            if ((key) > k1)      { k3 = k2; k2 = k1; k1 = (key); }             \
            else if ((key) > k2) { k3 = k2; k2 = (key); }                      \
            else                 { k3 = (key); }                               \
    } } while (0)

// ---------------------------------------------------------------------------
// prep_x: Xb = bf16(x - b_pre)
// ---------------------------------------------------------------------------
__global__ void prep_x(const float* __restrict__ X, const float* __restrict__ b_pre,
                       __nv_bfloat16* __restrict__ Xb)
{
    const int idx = blockIdx.x * blockDim.x + threadIdx.x;   // B*D/4 total
    const int d4  = idx % (D_DIM / 4);
    float4 x4 = reinterpret_cast<const float4*>(X)[idx];
    float4 bp = reinterpret_cast<const float4*>(b_pre)[d4];
    uint32_t lo = pack_bf2(x4.x - bp.x, x4.y - bp.y);
    uint32_t hi = pack_bf2(x4.z - bp.z, x4.w - bp.w);
    reinterpret_cast<uint2*>(Xb)[idx] = make_uint2(lo, hi);
}

// ---------------------------------------------------------------------------
// Transpose W_enc [D, F] -> WT fp32 [F, D] and Wb bf16 [F, D]
// ---------------------------------------------------------------------------
__global__ void transpose_kernel(const float* __restrict__ W, float* __restrict__ WT,
                                 __nv_bfloat16* __restrict__ Wb)
{
    __shared__ float tile[32][33];
    const int f0 = blockIdx.x * 32, d0 = blockIdx.y * 32;
    const int tx = threadIdx.x, ty = threadIdx.y;   // 32 x 8
    #pragma unroll
    for (int i = 0; i < 4; i++)
        tile[ty + 8 * i][tx] = W[(size_t)(d0 + ty + 8 * i) * F_DIM + f0 + tx];
    __syncthreads();
    #pragma unroll
    for (int i = 0; i < 4; i++) {
        float v = tile[tx][ty + 8 * i];
        size_t o = (size_t)(f0 + ty + 8 * i) * D_DIM + d0 + tx;
        WT[o] = v;
        Wb[o] = __float2bfloat16(v);
    }
}

// ---------------------------------------------------------------------------
// Encoder GEMM via mma.sync bf16: Hb = bf16(relu(Xb @ Wb^T + b_enc)),
// plus per-row tile maxima into g_tmax (bf16 bits; monotone vs stored Hb).
// CTA 128x128, BK=32, 8 warps (2m x 4n), cp.async double-buffer (round-11
// champion configuration).
// ---------------------------------------------------------------------------
__global__ __launch_bounds__(256)
void enc_gemm_mma(const __nv_bfloat16* __restrict__ Xb,
                  const __nv_bfloat16* __restrict__ Wb,
                  const float* __restrict__ b_enc,
                  __nv_bfloat16* __restrict__ Hb)
{
    __shared__ __align__(16) __nv_bfloat16 As[2][128 * 40];
    __shared__ __align__(16) __nv_bfloat16 Bs[2][128 * 40];
    __shared__ unsigned short tmaxs[128][17];

    const int tid = threadIdx.x, wid = tid >> 5, lane = tid & 31;
    const int row0 = blockIdx.x * 128, col0 = blockIdx.y * 128;
    const int warp_m = wid >> 2, warp_n = wid & 3;

    float acc[4][4][4];
    #pragma unroll
    for (int i = 0; i < 4; i++)
        #pragma unroll
        for (int j = 0; j < 4; j++)
            #pragma unroll
            for (int q = 0; q < 4; q++) acc[i][j][q] = 0.0f;

    const uint32_t sA[2] = { smem_u32(As[0]), smem_u32(As[1]) };
    const uint32_t sB[2] = { smem_u32(Bs[0]), smem_u32(Bs[1]) };

    const int lr0 = tid >> 2, lc0 = tid & 3;
    const int lr1 = (tid + 256) >> 2, lc1 = lc0;

    #define ISSUE(c, buf) do {                                                 \
        const int _k0 = (c) * 32;                                              \
        const __nv_bfloat16* aA0 = Xb + (size_t)(row0 + lr0) * D_DIM + _k0 + lc0 * 8; \
        const __nv_bfloat16* aA1 = Xb + (size_t)(row0 + lr1) * D_DIM + _k0 + lc1 * 8; \
        const __nv_bfloat16* aB0 = Wb + (size_t)(col0 + lr0) * D_DIM + _k0 + lc0 * 8; \
        const __nv_bfloat16* aB1 = Wb + (size_t)(col0 + lr1) * D_DIM + _k0 + lc1 * 8; \
        CP_ASYNC16(sA[buf] + lr0 * 80 + lc0 * 16, aA0);                        \
        CP_ASYNC16(sA[buf] + lr1 * 80 + lc1 * 16, aA1);                        \
        CP_ASYNC16(sB[buf] + lr0 * 80 + lc0 * 16, aB0);                        \
        CP_ASYNC16(sB[buf] + lr1 * 80 + lc1 * 16, aB1);                        \
        CP_COMMIT();                                                           \
    } while (0)

    ISSUE(0, 0);

    for (int c = 0; c < 24; c++) {
        const int buf = c & 1;
        if (c + 1 < 24) { ISSUE(c + 1, buf ^ 1); CP_WAIT(1); }
        else            { CP_WAIT(0); }
        __syncthreads();

        const uint32_t sa = sA[buf], sb = sB[buf];
        #pragma unroll
        for (int ks = 0; ks < 2; ks++) {
            uint32_t a[4][4], b[2][4];
            const uint32_t koff = (uint32_t)((ks * 16 + (lane >> 4) * 8) * 2);
            #pragma unroll
            for (int mf = 0; mf < 4; mf++) {
                const uint32_t r = (uint32_t)(warp_m * 64 + mf * 16 + (lane & 15));
                LDSM_X4(a[mf], sa + r * 80 + koff);
            }
            #pragma unroll
            for (int np = 0; np < 2; np++) {
                const uint32_t r = (uint32_t)(warp_n * 32 + np * 16 + (lane & 15));
                LDSM_X4(b[np], sb + r * 80 + koff);
            }
            #pragma unroll
            for (int mf = 0; mf < 4; mf++) {
                #pragma unroll
                for (int np = 0; np < 2; np++) {
                    MMA16816(acc[mf][np * 2 + 0], a[mf], b[np][0], b[np][2]);
                    MMA16816(acc[mf][np * 2 + 1], a[mf], b[np][1], b[np][3]);
                }
            }
        }
        __syncthreads();
    }
    #undef ISSUE

    // epilogue: + b_enc, relu, bf16 store; accumulate per-thread row maxima
    const int lr = lane >> 2, lc = (lane & 3) * 2;
    float rmax[8];
    #pragma unroll
    for (int i = 0; i < 8; i++) rmax[i] = 0.0f;   // relu => values >= 0

    #pragma unroll
    for (int nf = 0; nf < 4; nf++) {
        const int col = col0 + warp_n * 32 + nf * 8 + lc;
        const float e0 = b_enc[col], e1 = b_enc[col + 1];
        #pragma unroll
        for (int mf = 0; mf < 4; mf++) {
            const int row = row0 + warp_m * 64 + mf * 16 + lr;
            float v0 = fmaxf(acc[mf][nf][0] + e0, 0.0f);
            float v1 = fmaxf(acc[mf][nf][1] + e1, 0.0f);
            float v2 = fmaxf(acc[mf][nf][2] + e0, 0.0f);
            float v3 = fmaxf(acc[mf][nf][3] + e1, 0.0f);
            rmax[2 * mf]     = fmaxf(rmax[2 * mf],     fmaxf(v0, v1));
            rmax[2 * mf + 1] = fmaxf(rmax[2 * mf + 1], fmaxf(v2, v3));
            *reinterpret_cast<uint32_t*>(Hb + (size_t)row * F_DIM + col)       = pack_bf2(v0, v1);
            *reinterpret_cast<uint32_t*>(Hb + (size_t)(row + 8) * F_DIM + col) = pack_bf2(v2, v3);
        }
    }

    // per-row tile max: 16 slots per row (4 warp_n x 4 lane-groups)
    const int slot = warp_n * 4 + (lane & 3);
    #pragma unroll
    for (int i = 0; i < 8; i++) {
        const int r = warp_m * 64 + (i >> 1) * 16 + lr + (i & 1) * 8;
        tmaxs[r][slot] = __bfloat16_as_ushort(__float2bfloat16(rmax[i]));
    }
    __syncthreads();
    if (tid < 128) {
        unsigned short m = 0;
        #pragma unroll
        for (int s = 0; s < 16; s++) m = max(m, tmaxs[tid][s]);
        g_tmax[(size_t)(row0 + tid) * NTILE + blockIdx.y] = m;
    }
}

// ---------------------------------------------------------------------------
// sel_a: per row, tau = 40th-largest tile max; emit qualifying tile list.
// One warp per row (8 rows / 256-thread block).
// ---------------------------------------------------------------------------
__global__ __launch_bounds__(256)
void sel_a()
{
    const int warp = threadIdx.x >> 5, lane = threadIdx.x & 31;
    const int row = blockIdx.x * 8 + warp;
    __shared__ int cnt[8];
    if (lane == 0) cnt[warp] = 0;
    __syncwarp();

    uint32_t tmv[6];
    uint32_t k1 = 0u, k2 = 0u, k3 = 0u;
    #pragma unroll
    for (int i = 0; i < 6; i++) {
        tmv[i] = (uint32_t)g_tmax[(size_t)row * NTILE + i * 32 + lane];
        const uint32_t key = (tmv[i] << 8) | (uint32_t)(255 - (i * 32 + lane));
        K3_INSERT(key);
    }

    uint32_t tau = 0u;
    uint32_t lastpop = 0xffffffffu;
    for (int r = 0; r < NCAND; r++) {
        const uint32_t wk = __reduce_max_sync(0xffffffffu, k1);
        if (r == NCAND - 1) tau = wk >> 8;
        if (k1 == wk && wk != 0u) {
            lastpop = wk;
            if (k2 != 0u) { k1 = k2; k2 = k3; k3 = 0u; }
            else {
                k1 = k2 = k3 = 0u;
                #pragma unroll
                for (int i = 0; i < 6; i++) {
                    const uint32_t key = (tmv[i] << 8) | (uint32_t)(255 - (i * 32 + lane));
                    if (key < lastpop) K3_INSERT(key);
                }
            }
        }
    }

    #pragma unroll
    for (int i = 0; i < 6; i++)
        if (tmv[i] >= tau) {
            const int p = atomicAdd(&cnt[warp], 1);
            g_tlist[(size_t)row * NTILE + p] = (unsigned short)(i * 32 + lane);
        }
    __syncwarp();
    if (lane == 0) g_tcnt[row] = cnt[warp];
}

// ---------------------------------------------------------------------------
// sel_b: exact top-NCAND (value desc, index asc) over the qualifying tiles.
// Non-listed tiles provably contain no top-40 element (incl. bit-ties).
// ---------------------------------------------------------------------------
__global__ __launch_bounds__(256)
void sel_b(const __nv_bfloat16* __restrict__ Hb)
{
    const int row = blockIdx.x;
    const int t = threadIdx.x, lane = t & 31, warp = t >> 5;

    __shared__ unsigned short tl[NTILE];
    __shared__ int s_nt;
    __shared__ uint32_t cand[8 * NCAND];

    if (t == 0) s_nt = g_tcnt[row];
    __syncthreads();
    const int nt = s_nt;
    if (t < nt) tl[t] = g_tlist[(size_t)row * NTILE + t];
    __syncthreads();

    const uint4* __restrict__ hrow =
        reinterpret_cast<const uint4*>(Hb + (size_t)row * F_DIM);
    const int nq = nt * 16;           // uint4 chunks over listed tiles

    uint32_t k1 = 0u, k2 = 0u, k3 = 0u;
    for (int q = t; q < nq; q += 256) {
        const uint32_t u = (uint32_t)tl[q >> 4] * 16u + (uint32_t)(q & 15);
        uint4 d = hrow[u];
        uint32_t ws[4] = { d.x, d.y, d.z, d.w };
        #pragma unroll
        for (int w = 0; w < 4; w++) {
            #pragma unroll
            for (int e = 0; e < 2; e++) {
                const uint32_t vb  = e ? (ws[w] >> 16) : (ws[w] & 0xffffu);
                const uint32_t key = (vb << 15) | (uint32_t)(24575u - (u * 8u + (uint32_t)(w * 2 + e)));
                K3_INSERT(key);
            }
        }
    }

    uint32_t lastpop = 0xffffffffu;
    for (int r = 0; r < NCAND; r++) {
        const uint32_t wk = __reduce_max_sync(0xffffffffu, k1);
        if (lane == 0) cand[warp * NCAND + r] = wk;
        if (k1 == wk && wk != 0u) {
            lastpop = wk;
            if (k2 != 0u) { k1 = k2; k2 = k3; k3 = 0u; }
            else {
                k1 = k2 = k3 = 0u;
                for (int q = t; q < nq; q += 256) {
                    const uint32_t u = (uint32_t)tl[q >> 4] * 16u + (uint32_t)(q & 15);
                    uint4 d = hrow[u];
                    uint32_t ws[4] = { d.x, d.y, d.z, d.w };
                    #pragma unroll
                    for (int w = 0; w < 4; w++) {
                        #pragma unroll
                        for (int e = 0; e < 2; e++) {
                            const uint32_t vb  = e ? (ws[w] >> 16) : (ws[w] & 0xffffu);
                            const uint32_t key = (vb << 15) | (uint32_t)(24575u - (u * 8u + (uint32_t)(w * 2 + e)));
                            if (key < lastpop) K3_INSERT(key);
                        }
                    }
                }
            }
        }
    }
    __syncthreads();

    // warp 0 merges 8x40 -> block top-40 (keys globally unique)
    if (warp == 0) {
        uint32_t c[10];
        #pragma unroll
        for (int i = 0; i < 10; i++) c[i] = cand[i * 32 + lane];
        for (int r = 0; r < NCAND; r++) {
            uint32_t loc = 0u;
            #pragma unroll
            for (int i = 0; i < 10; i++) loc = max(loc, c[i]);
            const uint32_t best = __reduce_max_sync(0xffffffffu, loc);
            #pragma unroll
            for (int i = 0; i < 10; i++) if (c[i] == best) c[i] = 0u;
            if (lane == 0)
                g_ci[row * NCAND + r] = (int)(24575u - (best & 0x7fffu));
        }
    }
}

// ---------------------------------------------------------------------------
__global__ void zero_kernel(float4* __restrict__ p, size_t n4)
{
    size_t i = (size_t)blockIdx.x * blockDim.x + threadIdx.x;
    const size_t stride = (size_t)gridDim.x * blockDim.x;
    for (; i < n4; i += stride) p[i] = make_float4(0.f, 0.f, 0.f, 0.f);
}

// ---------------------------------------------------------------------------
// Exact recompute, BIT-IDENTICAL to the round-1 fp32 path:
// one thread per candidate, single fp32 accumulator, fmaf over k = 0..767
// ascending, then fmaxf(s + b_enc, 0). Then per-warp exact top-32 + scatter.
// ---------------------------------------------------------------------------
__global__ __launch_bounds__(320)
void exact_seq(const float* __restrict__ X, const float* __restrict__ b_pre,
               const float* __restrict__ WT, const float* __restrict__ b_enc,
               float* __restrict__ Hout)
{
    const int r0 = blockIdx.x * 8;
    const int t = threadIdx.x;
    const int lane = t & 31, w = t >> 5;

    __shared__ float xs[8][D_DIM];
    __shared__ float cv[8][NCAND];
    __shared__ int   ci[8][NCAND];

    for (int i = t; i < 8 * D_DIM; i += 320) {
        const int rr = i / D_DIM, k = i % D_DIM;
        xs[rr][k] = X[(size_t)(r0 + rr) * D_DIM + k] - b_pre[k];
    }
    if (t < 8 * NCAND) ci[t / NCAND][t % NCAND] = g_ci[(size_t)(r0 + t / NCAND) * NCAND + t % NCAND];
    __syncthreads();

    {   // all 320 threads: one candidate each, strict sequential fp32 chain
        const int rr = t / NCAND, c = t % NCAND;
        const int f = ci[rr][c];
        const float* __restrict__ wt = WT + (size_t)f * D_DIM;
        const float* __restrict__ xr = xs[rr];
        float s = 0.0f;
        #pragma unroll 4
        for (int k4 = 0; k4 < D_DIM / 4; k4++) {
            float4 w4 = reinterpret_cast<const float4*>(wt)[k4];
            float4 x4 = reinterpret_cast<const float4*>(xr)[k4];
            s = fmaf(w4.x, x4.x, s);
            s = fmaf(w4.y, x4.y, s);
            s = fmaf(w4.z, x4.z, s);
            s = fmaf(w4.w, x4.w, s);
        }
        cv[rr][c] = fmaxf(s + b_enc[f], 0.0f);
    }
    __syncthreads();

    // warps 0..7: exact top-32 of this row's 40 candidates (ties -> lower idx)
    if (w < 8) {
        const int row = r0 + w;
        uint64_t used = 0ull;
        for (int r2 = 0; r2 < TOPK; r2++) {
            float v = -1.0f; int idx = 0x7fffffff; int jslot = 63;
            {
                int j0 = lane;
                if (!((used >> j0) & 1ull)) { v = cv[w][j0]; idx = ci[w][j0]; jslot = j0; }
                if (lane < NCAND - 32) {
                    int j1 = 32 + lane;
                    if (!((used >> j1) & 1ull)) {
                        float v1 = cv[w][j1]; int k1 = ci[w][j1];
                        if (v1 > v || (v1 == v && k1 < idx)) { v = v1; idx = k1; jslot = j1; }
                    }
                }
            }
            #pragma unroll
            for (int s = 16; s > 0; s >>= 1) {
                float ov = __shfl_down_sync(0xffffffffu, v, s);
                int   oi = __shfl_down_sync(0xffffffffu, idx, s);
                int   oj = __shfl_down_sync(0xffffffffu, jslot, s);
                if (ov > v || (ov == v && oi < idx)) { v = ov; idx = oi; jslot = oj; }
            }
            int winj = __shfl_sync(0xffffffffu, jslot, 0);
            if (lane == 0) {
                g_tv[row * TOPK + r2] = v;
                g_ti[row * TOPK + r2] = idx;
                Hout[(size_t)row * F_DIM + idx] = v;
            }
            used |= (1ull << winj);
        }
    }
}

// ---------------------------------------------------------------------------
__global__ __launch_bounds__(256)
void dec_kernel(const float* __restrict__ Wd, const float* __restrict__ b_dec,
                float* __restrict__ Xhat)
{
    const int row = blockIdx.x;
    const int t = threadIdx.x;
    __shared__ float sv[TOPK];
    __shared__ int   si[TOPK];
    if (t < TOPK) { sv[t] = g_tv[row * TOPK + t]; si[t] = g_ti[row * TOPK + t]; }
    __syncthreads();

    float a0 = b_dec[t], a1 = b_dec[t + 256], a2 = b_dec[t + 512];
    #pragma unroll
    for (int j = 0; j < TOPK; j++) {
        const float* __restrict__ wr = Wd + (size_t)si[j] * D_DIM;
        float v = sv[j];
        a0 += v * wr[t];
        a1 += v * wr[t + 256];
        a2 += v * wr[t + 512];
    }
    float* __restrict__ xr = Xhat + (size_t)row * D_DIM;
    xr[t] = a0; xr[t + 256] = a1; xr[t + 512] = a2;
}

// ---------------------------------------------------------------------------
extern "C" void kernel_launch(void* const* d_in, const int* in_sizes, int n_in,
                              void* d_out, int out_size)
{
    const float* x     = (const float*)d_in[0];
    const float* b_pre = (const float*)d_in[1];
    const float* W_enc = (const float*)d_in[2];
    const float* b_enc = (const float*)d_in[3];
    const float* W_dec = (const float*)d_in[4];
    const float* b_dec = (const float*)d_in[5];
    float* out = (float*)d_out;

    const size_t needH = (size_t)B_ROWS * F_DIM;
    const size_t needX = (size_t)B_ROWS * D_DIM;
    float* H    = out;                            // out holds h (+ x_hat)
    float* Xhat = ((size_t)out_size >= needH + needX) ? out + needH : nullptr;

    float* WT = nullptr;          cudaGetSymbolAddress((void**)&WT, g_WT);
    __nv_bfloat16* Wb = nullptr;  cudaGetSymbolAddress((void**)&Wb, g_Wb);
    __nv_bfloat16* Xb = nullptr;  cudaGetSymbolAddress((void**)&Xb, g_Xb);
    __nv_bfloat16* Hb = nullptr;  cudaGetSymbolAddress((void**)&Hb, g_Hb);

    prep_x<<<(B_ROWS * D_DIM / 4) / 256, 256>>>(x, b_pre, Xb);
    transpose_kernel<<<dim3(F_DIM / 32, D_DIM / 32), dim3(32, 8)>>>(W_enc, WT, Wb);
    enc_gemm_mma<<<dim3(B_ROWS / 128, F_DIM / 128), 256>>>(Xb, Wb, b_enc, Hb);
    sel_a<<<B_ROWS / 8, 256>>>();
    sel_b<<<B_ROWS, 256>>>(Hb);
    zero_kernel<<<12288, 256>>>(reinterpret_cast<float4*>(H), needH / 4);
    exact_seq<<<B_ROWS / 8, 320>>>(x, b_pre, WT, b_enc, H);
    if (Xhat) dec_kernel<<<B_ROWS, 256>>>(W_dec, b_dec, Xhat);
}